// round 9
// baseline (speedup 1.0000x reference)
#include <cuda_runtime.h>
#include <cstdint>

#define NB 512
#define ND 256
#define NC 10
#define NSL 8              // timeline slices per batch-pair
#define NBLK (256 * NSL)   // kband grid

// ---------------------------------------------------------------------------
// packed fp32x2 helpers
// ---------------------------------------------------------------------------
typedef unsigned long long ps_t;

__device__ __forceinline__ ps_t pk2(float lo, float hi) {
    ps_t o; asm("mov.b64 %0,{%1,%2};" : "=l"(o) : "f"(lo), "f"(hi)); return o;
}
__device__ __forceinline__ void up2(ps_t a, float& lo, float& hi) {
    asm("mov.b64 {%0,%1},%2;" : "=f"(lo), "=f"(hi) : "l"(a));
}
__device__ __forceinline__ ps_t fma2(ps_t a, ps_t b, ps_t c) {
    ps_t d; asm("fma.rn.f32x2 %0,%1,%2,%3;" : "=l"(d) : "l"(a), "l"(b), "l"(c)); return d;
}
__device__ __forceinline__ ps_t add2(ps_t a, ps_t b) {
    ps_t d; asm("add.rn.f32x2 %0,%1,%2;" : "=l"(d) : "l"(a), "l"(b)); return d;
}
__device__ __forceinline__ ps_t relu2(ps_t a) {
    float l, h; up2(a, l, h);
    return pk2(fmaxf(l, 0.f), fmaxf(h, 0.f));
}

// packed weights: [0:10) w1, [10:20) b1, [20:110) w2[c*9+kh*3+kw], [110] b2
__constant__ ps_t c_pack[111];
__device__ ps_t g_pack[111];
__device__ float g_part[NBLK * 4];
__device__ float g_rs2[NB * ND];        // [pair][i][hb]
__device__ float g_csh[NB * ND * 2];    // [pair][half][j][hb]
__device__ unsigned int g_ctr;

// ---------------------------------------------------------------------------
// Kernel 1: row/col sums. grid=1024: block = (batch, row-half), 256 threads.
// ---------------------------------------------------------------------------
__global__ void __launch_bounds__(256) ksums(const float* __restrict__ x,
                                             const float* __restrict__ w1,
                                             const float* __restrict__ b1,
                                             const float* __restrict__ w2,
                                             const float* __restrict__ b2) {
    const int bid = blockIdx.x;
    const int b = bid >> 1;          // batch
    const int h = bid & 1;           // row half
    const int t = threadIdx.x;
    const int w = t >> 5;
    const int l = t & 31;
    const int bi = b >> 1;           // pair
    const int hb = b & 1;            // lane within pair

    if (bid == 0) {   // weight packing (tiny)
        if (t < 10) { g_pack[t] = pk2(w1[t], w1[t]); g_pack[10 + t] = pk2(b1[t], b1[t]); }
        if (t < 90) g_pack[20 + t] = pk2(w2[t], w2[t]);
        if (t == 0) g_pack[110] = pk2(b2[0], b2[0]);
    }

    __shared__ float scs[8 * 256];
    const float4* __restrict__ xb =
        reinterpret_cast<const float4*>(x + (size_t)b * (ND * ND));

    float ca[8];
#pragma unroll
    for (int k = 0; k < 8; ++k) ca[k] = 0.f;

    const int i0 = 128 * h + 16 * w;
#pragma unroll 4
    for (int ri = 0; ri < 16; ++ri) {
        const int i = i0 + ri;
        float4 v0 = xb[i * 64 + 2 * l];
        float4 v1 = xb[i * 64 + 2 * l + 1];
        ca[0] += v0.x; ca[1] += v0.y; ca[2] += v0.z; ca[3] += v0.w;
        ca[4] += v1.x; ca[5] += v1.y; ca[6] += v1.z; ca[7] += v1.w;
        float rsum = (v0.x + v0.y) + (v0.z + v0.w) + (v1.x + v1.y) + (v1.z + v1.w);
#pragma unroll
        for (int o = 16; o; o >>= 1) rsum += __shfl_xor_sync(0xffffffffu, rsum, o);
        if (l == 0) g_rs2[bi * 512 + i * 2 + hb] = rsum;
    }
#pragma unroll
    for (int k = 0; k < 8; ++k) scs[w * 256 + 8 * l + k] = ca[k];
    __syncthreads();
    float c = 0.f;
#pragma unroll
    for (int ww = 0; ww < 8; ++ww) c += scs[ww * 256 + t];
    g_csh[((bi * 2 + h) * 256 + t) * 2 + hb] = c;
}

// ---------------------------------------------------------------------------
// fast tap: all weights from shared via broadcast LDS.128 (2 packed wts/load)
// w1b1: [cc] -> {w1 pair, b1 pair}; w2e: 15 ulonglong2 [d][cpair]
// ---------------------------------------------------------------------------
__device__ __forceinline__ void tapf(const ulonglong2* __restrict__ w1b1,
                                     const ulonglong2* __restrict__ w2e,
                                     ps_t tv, ps_t& A0, ps_t& A1, ps_t& A2) {
#pragma unroll
    for (int cc = 0; cc < 5; ++cc) {
        ulonglong2 wp = w1b1[2 * cc];
        ulonglong2 bp = w1b1[2 * cc + 1];
        ps_t ga = relu2(fma2(wp.x, tv, bp.x));
        ps_t gb = relu2(fma2(wp.y, tv, bp.y));
        ulonglong2 p0 = w2e[0 * 5 + cc];
        ulonglong2 p1 = w2e[1 * 5 + cc];
        ulonglong2 p2 = w2e[2 * 5 + cc];
        A0 = fma2(p0.x, ga, A0); A0 = fma2(p0.y, gb, A0);
        A1 = fma2(p1.x, ga, A1); A1 = fma2(p1.y, gb, A1);
        A2 = fma2(p2.x, ga, A2); A2 = fma2(p2.y, gb, A2);
    }
}

// ---------------------------------------------------------------------------
// fast column sweep with peeled guards.
// Emits rows i=p-1 for p in [ef, pend]; warmup iters [pstartW, pbeg) no-emit.
// EDGE: column may be 0 (vm false) -> e0 tap guarded in steady loop too.
// ---------------------------------------------------------------------------
template <bool EDGE>
__device__ __forceinline__ void run_fast(
    int c, int pstartW, int pbeg, int pend, int ef, bool addcorr, bool vm,
    ps_t csm, ps_t cs0, ps_t csp,
    const ps_t* __restrict__ srs, const ps_t (*__restrict__ sW)[4],
    const ulonglong2* __restrict__ sw1b1,
    const ulonglong2 (*__restrict__ sw2)[3][5],
    ps_t b2v, float c0,
    ps_t& acc0, ps_t& acc1, ps_t& acc2, ps_t& acc3) {

    ps_t wj0, wj1, wj2, wj3;
    {
        const ulonglong2* wr = (const ulonglong2*)&sW[c][0];
        ulonglong2 wa = wr[0], wb = wr[1];
        wj0 = wa.x; wj1 = wa.y; wj2 = wb.x; wj3 = wb.y;
    }

    ps_t pend1 = 0ULL, a0last = 0ULL, ycol = 0ULL;

    // guarded region: warmup + head (tap staggering + band mask)
    int gend = pend < c ? pend : c;
    {   int g2 = pbeg - 1;  if (g2 > gend) gend = g2; }
    if (gend > 255) gend = 255;

    int p = pstartW;
    for (; p <= gend; ++p) {
        ps_t A0 = 0ULL, A1 = 0ULL, A2 = 0ULL;
        const ps_t rsp = srs[p];
        if ((!EDGE || vm) && p >= c - 1) tapf(sw1b1, &sw2[0][0][0], add2(rsp, csm), A0, A1, A2);
        if (p >= c)                      tapf(sw1b1, &sw2[1][0][0], add2(rsp, cs0), A0, A1, A2);
        if (p >= c + 1)                  tapf(sw1b1, &sw2[2][0][0], add2(rsp, csp), A0, A1, A2);
        if (p >= ef) {
            ps_t y = relu2(add2(add2(pend1, A2), b2v));
            ps_t yc = (c <= p + 1) ? y : 0ULL;
            ycol = add2(ycol, yc);
            const ulonglong2* wr = (const ulonglong2*)&sW[p - 1][0];
            ulonglong2 wa = wr[0], wb = wr[1];
            acc0 = fma2(yc, wa.x, acc0); acc1 = fma2(yc, wa.y, acc1);
            acc2 = fma2(yc, wb.x, acc2); acc3 = fma2(yc, wb.y, acc3);
        }
        pend1 = add2(A1, a0last);
        a0last = A0;
    }

    // steady region: all taps active, emit unmasked (p >= ef guaranteed)
    const int send = pend < 255 ? pend : 255;
    for (; p <= send; ++p) {
        ps_t A0 = 0ULL, A1 = 0ULL, A2 = 0ULL;
        const ps_t rsp = srs[p];
        if (!EDGE || vm) tapf(sw1b1, &sw2[0][0][0], add2(rsp, csm), A0, A1, A2);
        tapf(sw1b1, &sw2[1][0][0], add2(rsp, cs0), A0, A1, A2);
        tapf(sw1b1, &sw2[2][0][0], add2(rsp, csp), A0, A1, A2);

        ps_t y = relu2(add2(add2(pend1, A2), b2v));
        ycol = add2(ycol, y);
        const ulonglong2* wr = (const ulonglong2*)&sW[p - 1][0];
        ulonglong2 wa = wr[0], wb = wr[1];
        acc0 = fma2(y, wa.x, acc0); acc1 = fma2(y, wa.y, acc1);
        acc2 = fma2(y, wb.x, acc2); acc3 = fma2(y, wb.y, acc3);

        pend1 = add2(A1, a0last);
        a0last = A0;
    }

    // flush: p == 256 emits row 255 (no taps)
    if (pend == 256) {
        ps_t y = relu2(add2(pend1, b2v));
        ycol = add2(ycol, y);
        const ulonglong2* wr = (const ulonglong2*)&sW[255][0];
        ulonglong2 wa = wr[0], wb = wr[1];
        acc0 = fma2(y, wa.x, acc0); acc1 = fma2(y, wa.y, acc1);
        acc2 = fma2(y, wb.x, acc2); acc3 = fma2(y, wb.y, acc3);
    }

    if (addcorr) {
        const int rn = (253 - c) > 0 ? (253 - c) : 0;
        const int cn = (c - 2) > 0 ? (c - 2) : 0;
        const float cf = c0 * (float)(rn + cn);
        ycol = add2(ycol, pk2(cf, cf));
    }
    acc0 = fma2(ycol, wj0, acc0); acc1 = fma2(ycol, wj1, acc1);
    acc2 = fma2(ycol, wj2, acc2); acc3 = fma2(ycol, wj3, acc3);
}

// ---------------------------------------------------------------------------
// Kernel 2: band conv + fused fc1 + fused final fc2 (last-block reduction).
// grid = 2048 (= 256 pairs x 8 slices), 128 threads.
// __launch_bounds__(128, 8): 64-reg budget — enough to avoid spill (R6 ran at
// 60), tight enough that ptxas cannot hoist the 75 broadcast LDS.128 weight
// loads into registers (R8 failure), and 8 blocks/SM residency (R7/R8 fix).
// ---------------------------------------------------------------------------
__global__ void __launch_bounds__(128, 8) kband(const float* __restrict__ fc1w,
                                                const float* __restrict__ fc1b,
                                                const float* __restrict__ fc2w,
                                                const float* __restrict__ fc2b,
                                                float* __restrict__ out) {
    const int bid = blockIdx.x;
    const int pair = bid >> 3;
    const int s = bid & 7;

    const int t = threadIdx.x;
    const int w = t >> 5;
    const int lane = t & 31;
    const int q = t;                 // low column of the pair (q, 255-q)

    __shared__ ps_t srs[ND];
    __shared__ ps_t scs[ND];
    __shared__ ps_t sW[ND][4];
    __shared__ ulonglong2 sw2[3][3][5];   // [e][d][cpair]
    __shared__ ulonglong2 sw1b1[10];      // [cc] -> {w1 pair}, {b1 pair}
    __shared__ ps_t sred[4][4];
    __shared__ int lastf;

#pragma unroll
    for (int r = 0; r < 2; ++r) {
        const int i = t + 128 * r;
        srs[i] = ((const ps_t*)g_rs2)[pair * 256 + i];
        scs[i] = add2(((const ps_t*)g_csh)[(pair * 2 + 0) * 256 + i],
                      ((const ps_t*)g_csh)[(pair * 2 + 1) * 256 + i]);
    }
    if (t < 90) {
        const int e = t / 30, r = t % 30, d = r / 10, c = r % 10;
        ((ps_t*)sw2)[(e * 3 + d) * 10 + c] = c_pack[20 + c * 9 + d * 3 + e];
    }
    if (t < 5) {
        ((ps_t*)sw1b1)[4 * t + 0] = c_pack[2 * t];
        ((ps_t*)sw1b1)[4 * t + 1] = c_pack[2 * t + 1];
        ((ps_t*)sw1b1)[4 * t + 2] = c_pack[10 + 2 * t];
        ((ps_t*)sw1b1)[4 * t + 3] = c_pack[10 + 2 * t + 1];
    }
    const int b0 = 2 * pair;
    for (int idx = t; idx < 1024; idx += 128) {
        const int i = idx >> 2, k = idx & 3;
        sW[i][k] = pk2(fc1w[(size_t)k * 131072 + b0 * 256 + i],
                       fc1w[(size_t)k * 131072 + (b0 + 1) * 256 + i]);
    }
    __syncthreads();

    const ps_t b2v = c_pack[110];
    float b2f, b2d; up2(b2v, b2f, b2d);
    const float c0 = fmaxf(b2f, 0.f);

    ps_t acc0 = 0ULL, acc1 = 0ULL, acc2 = 0ULL, acc3 = 0ULL;
    const bool edge = (w == 0);

    // virtual timeline: part A = col q over p in [pA0, 256]; part B = col 255-q
    const int pA0 = (q - 3 > 0) ? (q - 3) : 0;
    const int iterA = 257 - pA0;
    const int iterB = q + 5;           // pB0 = 252 - q
    const int tot = iterA + iterB;
    const int v0 = (tot * s) >> 3;
    const int v1 = (tot * (s + 1)) >> 3;

    // ---- part A: column q ----
    {
        const int a0 = v0;
        const int a1 = (v1 < iterA) ? v1 : iterA;
        if (a0 < a1) {
            const int c = q;
            const int pbeg = pA0 + a0;
            const int pend = pA0 + a1 - 1;
            const int pstartW = (a0 == 0) ? pbeg : ((pbeg - 2 > 0) ? pbeg - 2 : 0);
            const int ef = (pbeg > 1) ? pbeg : 1;
            const bool vm = (c >= 1);
            const ps_t csm = vm ? scs[c - 1] : 0ULL;
            const ps_t cs0v = scs[c];
            const ps_t csp = (c <= 254) ? scs[c + 1] : 0ULL;
            if (edge)
                run_fast<true>(c, pstartW, pbeg, pend, ef, a0 == 0, vm, csm, cs0v, csp,
                               srs, sW, sw1b1, sw2, b2v, c0, acc0, acc1, acc2, acc3);
            else
                run_fast<false>(c, pstartW, pbeg, pend, ef, a0 == 0, vm, csm, cs0v, csp,
                                srs, sW, sw1b1, sw2, b2v, c0, acc0, acc1, acc2, acc3);
        }
    }
    // ---- part B: column 255 - q ----
    {
        const int u0 = (v0 > iterA) ? (v0 - iterA) : 0;
        const int u1 = v1 - iterA;
        if (u1 > u0) {
            const int c = 255 - q;
            const int pB0 = 252 - q;
            const int pbeg = pB0 + u0;
            const int pend = pB0 + u1 - 1;
            const int pstartW = (u0 == 0) ? pbeg : ((pbeg - 2 > 0) ? pbeg - 2 : 0);
            const int ef = (pbeg > 1) ? pbeg : 1;
            const bool vm = (c >= 1);
            const ps_t csm = vm ? scs[c - 1] : 0ULL;
            const ps_t cs0v = scs[c];
            const ps_t csp = (c <= 254) ? scs[c + 1] : 0ULL;
            if (edge)
                run_fast<true>(c, pstartW, pbeg, pend, ef, u0 == 0, vm, csm, cs0v, csp,
                               srs, sW, sw1b1, sw2, b2v, c0, acc0, acc1, acc2, acc3);
            else
                run_fast<false>(c, pstartW, pbeg, pend, ef, u0 == 0, vm, csm, cs0v, csp,
                                srs, sW, sw1b1, sw2, b2v, c0, acc0, acc1, acc2, acc3);
        }
    }

    // reduce acc across lanes, then across the 4 warps
    ps_t accv[4] = {acc0, acc1, acc2, acc3};
#pragma unroll
    for (int k = 0; k < 4; ++k) {
#pragma unroll
        for (int o = 16; o; o >>= 1)
            accv[k] = add2(accv[k], __shfl_xor_sync(0xffffffffu, accv[k], o));
    }
    if (lane == 0) {
#pragma unroll
        for (int k = 0; k < 4; ++k) sred[w][k] = accv[k];
    }
    __syncthreads();
    if (t < 4) {
        ps_t sv = add2(add2(sred[0][t], sred[1][t]), add2(sred[2][t], sred[3][t]));
        float lo, hi; up2(sv, lo, hi);
        g_part[bid * 4 + t] = lo + hi;
    }

    // ------- last-block final reduction + fc2 -------
    __threadfence();
    __syncthreads();
    if (t == 0) {
        unsigned int o = atomicAdd(&g_ctr, 1u);
        lastf = (o == (unsigned)(NBLK - 1)) ? 1 : 0;
    }
    __syncthreads();
    if (lastf) {
        float sv = 0.f;
        for (int i = lane; i < NBLK; i += 32) sv += g_part[i * 4 + w];
#pragma unroll
        for (int o = 16; o; o >>= 1) sv += __shfl_xor_sync(0xffffffffu, sv, o);
        __shared__ float fsh[4];
        if (lane == 0) fsh[w] = sv;
        __syncthreads();
        if (t == 0) {
            float h0 = fmaxf(fsh[0] + fc1b[0], 0.f);
            float h1 = fmaxf(fsh[1] + fc1b[1], 0.f);
            float h2 = fmaxf(fsh[2] + fc1b[2], 0.f);
            float h3 = fmaxf(fsh[3] + fc1b[3], 0.f);
            out[0] = fc2w[0] * h0 + fc2w[1] * h1 + fc2w[2] * h2 + fc2w[3] * h3 + fc2b[0];
            out[1] = fc2w[4] * h0 + fc2w[5] * h1 + fc2w[6] * h2 + fc2w[7] * h3 + fc2b[1];
            g_ctr = 0;   // reset for next launch/replay
        }
    }
}

// ---------------------------------------------------------------------------
extern "C" void kernel_launch(void* const* d_in, const int* in_sizes, int n_in,
                              void* d_out, int out_size) {
    const float* x    = (const float*)d_in[0];
    const float* w1   = (const float*)d_in[1];
    const float* b1   = (const float*)d_in[2];
    const float* w2   = (const float*)d_in[3];
    const float* b2   = (const float*)d_in[4];
    const float* fc1w = (const float*)d_in[5];
    const float* fc1b = (const float*)d_in[6];
    const float* fc2w = (const float*)d_in[7];
    const float* fc2b = (const float*)d_in[8];

    ksums<<<2 * NB, 256>>>(x, w1, b1, w2, b2);

    void* gp = nullptr;
    cudaGetSymbolAddress(&gp, g_pack);
    cudaMemcpyToSymbolAsync(c_pack, gp, 111 * sizeof(ps_t), 0,
                            cudaMemcpyDeviceToDevice, 0);

    kband<<<NBLK, 128>>>(fc1w, fc1b, fc2w, fc2b, (float*)d_out);
}

// round 10
// speedup vs baseline: 6.9782x; 6.9782x over previous
#include <cuda_runtime.h>
#include <cstdint>

#define NB 512
#define ND 256
#define NC 10
#define NSL 4              // timeline slices per batch-pair (R5 optimum)
#define NBLK (256 * NSL)   // kband grid

// ---------------------------------------------------------------------------
// packed fp32x2 helpers
// ---------------------------------------------------------------------------
typedef unsigned long long ps_t;

__device__ __forceinline__ ps_t pk2(float lo, float hi) {
    ps_t o; asm("mov.b64 %0,{%1,%2};" : "=l"(o) : "f"(lo), "f"(hi)); return o;
}
__device__ __forceinline__ void up2(ps_t a, float& lo, float& hi) {
    asm("mov.b64 {%0,%1},%2;" : "=f"(lo), "=f"(hi) : "l"(a));
}
__device__ __forceinline__ ps_t fma2(ps_t a, ps_t b, ps_t c) {
    ps_t d; asm("fma.rn.f32x2 %0,%1,%2,%3;" : "=l"(d) : "l"(a), "l"(b), "l"(c)); return d;
}
__device__ __forceinline__ ps_t add2(ps_t a, ps_t b) {
    ps_t d; asm("add.rn.f32x2 %0,%1,%2;" : "=l"(d) : "l"(a), "l"(b)); return d;
}
__device__ __forceinline__ ps_t relu2(ps_t a) {
    float l, h; up2(a, l, h);
    return pk2(fmaxf(l, 0.f), fmaxf(h, 0.f));
}

// packed weights: [0:10) w1, [10:20) b1, [20:110) w2[c*9+kh*3+kw], [110] b2
__constant__ ps_t c_pack[111];
__device__ ps_t g_pack[111];
__device__ float g_part[NBLK * 4];
__device__ float g_rs2[NB * ND];        // [pair][i][hb]
__device__ float g_csh[NB * ND * 2];    // [pair][half][j][hb]
__device__ unsigned int g_ctr;

// ---------------------------------------------------------------------------
// Kernel 1: row/col sums. grid=1024: block = (batch, row-half), 256 threads.
// Col sums written as per-half partials (combined in kband preload).
// ---------------------------------------------------------------------------
__global__ void __launch_bounds__(256) ksums(const float* __restrict__ x,
                                             const float* __restrict__ w1,
                                             const float* __restrict__ b1,
                                             const float* __restrict__ w2,
                                             const float* __restrict__ b2) {
    const int bid = blockIdx.x;
    const int b = bid >> 1;          // batch
    const int h = bid & 1;           // row half
    const int t = threadIdx.x;
    const int w = t >> 5;
    const int l = t & 31;
    const int bi = b >> 1;           // pair
    const int hb = b & 1;            // lane within pair

    if (bid == 0) {   // weight packing (tiny)
        if (t < 10) { g_pack[t] = pk2(w1[t], w1[t]); g_pack[10 + t] = pk2(b1[t], b1[t]); }
        if (t < 90) g_pack[20 + t] = pk2(w2[t], w2[t]);
        if (t == 0) g_pack[110] = pk2(b2[0], b2[0]);
    }

    __shared__ float scs[8 * 256];
    const float4* __restrict__ xb =
        reinterpret_cast<const float4*>(x + (size_t)b * (ND * ND));

    float ca[8];
#pragma unroll
    for (int k = 0; k < 8; ++k) ca[k] = 0.f;

    const int i0 = 128 * h + 16 * w;
#pragma unroll 4
    for (int ri = 0; ri < 16; ++ri) {
        const int i = i0 + ri;
        float4 v0 = xb[i * 64 + 2 * l];
        float4 v1 = xb[i * 64 + 2 * l + 1];
        ca[0] += v0.x; ca[1] += v0.y; ca[2] += v0.z; ca[3] += v0.w;
        ca[4] += v1.x; ca[5] += v1.y; ca[6] += v1.z; ca[7] += v1.w;
        float rsum = (v0.x + v0.y) + (v0.z + v0.w) + (v1.x + v1.y) + (v1.z + v1.w);
#pragma unroll
        for (int o = 16; o; o >>= 1) rsum += __shfl_xor_sync(0xffffffffu, rsum, o);
        if (l == 0) g_rs2[bi * 512 + i * 2 + hb] = rsum;
    }
#pragma unroll
    for (int k = 0; k < 8; ++k) scs[w * 256 + 8 * l + k] = ca[k];
    __syncthreads();
    float c = 0.f;
#pragma unroll
    for (int ww = 0; ww < 8; ++ww) c += scs[ww * 256 + t];
    g_csh[((bi * 2 + h) * 256 + t) * 2 + hb] = c;
}

// ---------------------------------------------------------------------------
// tap: 10-ch generate + 3-row accumulate for one conv column e (LDC weights,
// the R5-proven form — natural register allocation, no spill)
// ---------------------------------------------------------------------------
__device__ __forceinline__ void tap2(ps_t t2, int e, ps_t& A0, ps_t& A1, ps_t& A2) {
#pragma unroll
    for (int c = 0; c < NC; ++c) {
        ps_t g = relu2(fma2(c_pack[c], t2, c_pack[10 + c]));
        A0 = fma2(c_pack[20 + c * 9 + 0 + e], g, A0);
        A1 = fma2(c_pack[20 + c * 9 + 3 + e], g, A1);
        A2 = fma2(c_pack[20 + c * 9 + 6 + e], g, A2);
    }
}

// ---------------------------------------------------------------------------
// sweep a p-range of column c. Emits rows i=p-1 for p in [emit_from, pend].
// pstart may include warmup iterations to refill the rolling pipeline.
// ---------------------------------------------------------------------------
__device__ __forceinline__ void run_col(
    int c, int pstart, int pend, int emit_from, bool addcorr,
    const ps_t* __restrict__ srs, const ps_t* __restrict__ scs,
    const ps_t (*__restrict__ sW)[4],
    ps_t b2v, float c0, ps_t acc[4]) {

    ps_t wj[4];
#pragma unroll
    for (int k = 0; k < 4; ++k) wj[k] = sW[c][k];

    const bool vm = (c >= 1);
    const bool vp = (c <= 254);
    const ps_t csm = vm ? scs[c - 1] : 0ULL;
    const ps_t cs0 = scs[c];
    const ps_t csp = vp ? scs[c + 1] : 0ULL;

    ps_t pend1 = 0ULL, a0last = 0ULL, ycol = 0ULL;

#pragma unroll 2
    for (int p = pstart; p <= pend; ++p) {
        ps_t A0 = 0ULL, A1 = 0ULL, A2 = 0ULL;
        if (p <= 255) {
            const ps_t rsp = srs[p];
            if (vm && (c - 1) <= p) tap2(add2(rsp, csm), 0, A0, A1, A2);
            if (c <= p)             tap2(add2(rsp, cs0), 1, A0, A1, A2);
            if (vp && (c + 1) <= p) tap2(add2(rsp, csp), 2, A0, A1, A2);
        }
        if (p >= emit_from) {
            ps_t y = relu2(add2(add2(pend1, A2), b2v));
            ps_t yc = (c <= p + 1) ? y : 0ULL;
            ycol = add2(ycol, yc);
            const ps_t* w4 = sW[p - 1];
#pragma unroll
            for (int k = 0; k < 4; ++k) acc[k] = fma2(yc, w4[k], acc[k]);
        }
        pend1 = add2(A1, a0last);
        a0last = A0;
    }

    if (addcorr) {
        const int rn = (253 - c) > 0 ? (253 - c) : 0;
        const int cn = (c - 2) > 0 ? (c - 2) : 0;
        const float cf = c0 * (float)(rn + cn);
        ycol = add2(ycol, pk2(cf, cf));
    }
#pragma unroll
    for (int k = 0; k < 4; ++k) acc[k] = fma2(ycol, wj[k], acc[k]);
}

// ---------------------------------------------------------------------------
// Kernel 2: band conv + fused fc1 + fused final fc2 (last-block reduction).
// grid = 1024 (= 256 pairs x 4 slices), 128 threads. Natural registers.
// ---------------------------------------------------------------------------
__global__ void __launch_bounds__(128) kband(const float* __restrict__ fc1w,
                                             const float* __restrict__ fc1b,
                                             const float* __restrict__ fc2w,
                                             const float* __restrict__ fc2b,
                                             float* __restrict__ out) {
    const int bid = blockIdx.x;
    const int pair = bid >> 2;
    const int s = bid & 3;

    const int t = threadIdx.x;
    const int w = t >> 5;
    const int lane = t & 31;
    const int q = t;                 // low column of the pair (q, 255-q)

    __shared__ ps_t srs[ND];
    __shared__ ps_t scs[ND];
    __shared__ ps_t sW[ND][4];
    __shared__ ps_t sred[4][4];
    __shared__ int lastf;

#pragma unroll
    for (int r = 0; r < 2; ++r) {
        const int i = t + 128 * r;
        srs[i] = ((const ps_t*)g_rs2)[pair * 256 + i];
        scs[i] = add2(((const ps_t*)g_csh)[(pair * 2 + 0) * 256 + i],
                      ((const ps_t*)g_csh)[(pair * 2 + 1) * 256 + i]);
    }
    const int b0 = 2 * pair;
    for (int idx = t; idx < 1024; idx += 128) {
        const int i = idx >> 2, k = idx & 3;
        sW[i][k] = pk2(fc1w[(size_t)k * 131072 + b0 * 256 + i],
                       fc1w[(size_t)k * 131072 + (b0 + 1) * 256 + i]);
    }
    __syncthreads();

    const ps_t b2v = c_pack[110];
    float b2f, b2d; up2(b2v, b2f, b2d);
    const float c0 = fmaxf(b2f, 0.f);

    ps_t acc[4] = {0ULL, 0ULL, 0ULL, 0ULL};

    // virtual timeline: part A = col q over p in [pA0, 256]; part B = col 255-q
    const int pA0 = (q - 3 > 0) ? (q - 3) : 0;
    const int iterA = 257 - pA0;
    const int iterB = q + 5;           // pB0 = 252 - q
    const int tot = iterA + iterB;
    const int v0 = (tot * s) >> 2;
    const int v1 = (tot * (s + 1)) >> 2;

    // part A overlap [v0, min(v1, iterA))
    {
        const int a0 = v0;
        const int a1 = (v1 < iterA) ? v1 : iterA;
        if (a0 < a1) {
            const int pbeg = pA0 + a0;
            const int pend = pA0 + a1 - 1;
            const int pstart = (a0 == 0) ? pbeg : ((pbeg - 2 > 0) ? pbeg - 2 : 0);
            const int ef = (pbeg > 1) ? pbeg : 1;
            run_col(q, pstart, pend, ef, a0 == 0, srs, scs, sW, b2v, c0, acc);
        }
    }
    // part B overlap [max(v0, iterA), v1)
    {
        const int u0 = (v0 > iterA) ? (v0 - iterA) : 0;
        const int u1 = v1 - iterA;
        if (u1 > u0) {
            const int pB0 = 252 - q;
            const int pbeg = pB0 + u0;
            const int pend = pB0 + u1 - 1;
            const int pstart = (u0 == 0) ? pbeg : ((pbeg - 2 > 0) ? pbeg - 2 : 0);
            const int ef = (pbeg > 1) ? pbeg : 1;
            run_col(255 - q, pstart, pend, ef, u0 == 0, srs, scs, sW, b2v, c0, acc);
        }
    }

    // reduce acc across lanes, then across the 4 warps
#pragma unroll
    for (int k = 0; k < 4; ++k) {
#pragma unroll
        for (int o = 16; o; o >>= 1)
            acc[k] = add2(acc[k], __shfl_xor_sync(0xffffffffu, acc[k], o));
    }
    if (lane == 0) {
#pragma unroll
        for (int k = 0; k < 4; ++k) sred[w][k] = acc[k];
    }
    __syncthreads();
    if (t < 4) {
        ps_t sv = add2(add2(sred[0][t], sred[1][t]), add2(sred[2][t], sred[3][t]));
        float lo, hi; up2(sv, lo, hi);
        g_part[bid * 4 + t] = lo + hi;
    }

    // ------- last-block final reduction + fc2 -------
    __threadfence();
    __syncthreads();
    if (t == 0) {
        unsigned int o = atomicAdd(&g_ctr, 1u);
        lastf = (o == (unsigned)(NBLK - 1)) ? 1 : 0;
    }
    __syncthreads();
    if (lastf) {
        float sv = 0.f;
        for (int i = lane; i < NBLK; i += 32) sv += g_part[i * 4 + w];
#pragma unroll
        for (int o = 16; o; o >>= 1) sv += __shfl_xor_sync(0xffffffffu, sv, o);
        __shared__ float fsh[4];
        if (lane == 0) fsh[w] = sv;
        __syncthreads();
        if (t == 0) {
            float h0 = fmaxf(fsh[0] + fc1b[0], 0.f);
            float h1 = fmaxf(fsh[1] + fc1b[1], 0.f);
            float h2 = fmaxf(fsh[2] + fc1b[2], 0.f);
            float h3 = fmaxf(fsh[3] + fc1b[3], 0.f);
            out[0] = fc2w[0] * h0 + fc2w[1] * h1 + fc2w[2] * h2 + fc2w[3] * h3 + fc2b[0];
            out[1] = fc2w[4] * h0 + fc2w[5] * h1 + fc2w[6] * h2 + fc2w[7] * h3 + fc2b[1];
            g_ctr = 0;   // reset for next launch/replay
        }
    }
}

// ---------------------------------------------------------------------------
extern "C" void kernel_launch(void* const* d_in, const int* in_sizes, int n_in,
                              void* d_out, int out_size) {
    const float* x    = (const float*)d_in[0];
    const float* w1   = (const float*)d_in[1];
    const float* b1   = (const float*)d_in[2];
    const float* w2   = (const float*)d_in[3];
    const float* b2   = (const float*)d_in[4];
    const float* fc1w = (const float*)d_in[5];
    const float* fc1b = (const float*)d_in[6];
    const float* fc2w = (const float*)d_in[7];
    const float* fc2b = (const float*)d_in[8];

    ksums<<<2 * NB, 256>>>(x, w1, b1, w2, b2);

    void* gp = nullptr;
    cudaGetSymbolAddress(&gp, g_pack);
    cudaMemcpyToSymbolAsync(c_pack, gp, 111 * sizeof(ps_t), 0,
                            cudaMemcpyDeviceToDevice, 0);

    kband<<<NBLK, 128>>>(fc1w, fc1b, fc2w, fc2b, (float*)d_out);
}

// round 12
// speedup vs baseline: 7.0584x; 1.0115x over previous
#include <cuda_runtime.h>
#include <cstdint>

#define NB 512
#define ND 256
#define NC 10
#define NSL 4              // timeline slices per batch-pair (R5/R10 optimum)
#define NBLK (256 * NSL)   // kband grid

// ---------------------------------------------------------------------------
// packed fp32x2 helpers
// ---------------------------------------------------------------------------
typedef unsigned long long ps_t;

__device__ __forceinline__ ps_t pk2(float lo, float hi) {
    ps_t o; asm("mov.b64 %0,{%1,%2};" : "=l"(o) : "f"(lo), "f"(hi)); return o;
}
__device__ __forceinline__ void up2(ps_t a, float& lo, float& hi) {
    asm("mov.b64 {%0,%1},%2;" : "=f"(lo), "=f"(hi) : "l"(a));
}
__device__ __forceinline__ ps_t fma2(ps_t a, ps_t b, ps_t c) {
    ps_t d; asm("fma.rn.f32x2 %0,%1,%2,%3;" : "=l"(d) : "l"(a), "l"(b), "l"(c)); return d;
}
__device__ __forceinline__ ps_t add2(ps_t a, ps_t b) {
    ps_t d; asm("add.rn.f32x2 %0,%1,%2;" : "=l"(d) : "l"(a), "l"(b)); return d;
}
__device__ __forceinline__ ps_t relu2(ps_t a) {   // 2x FMNMX (R10-proven)
    float l, h; up2(a, l, h);
    return pk2(fmaxf(l, 0.f), fmaxf(h, 0.f));
}

// ---------------------------------------------------------------------------
// constant weights, LDC.128-friendly layout (channel-PAIR vectors):
//   c_w1p[cc]       = { w1pack[2cc], w1pack[2cc+1] }
//   c_b1p[cc]       = { b1pack[2cc], b1pack[2cc+1] }
//   c_w2p[e][d][cc] = { w2pack[2cc][d][e], w2pack[2cc+1][d][e] }
// ---------------------------------------------------------------------------
__constant__ ulonglong2 c_w1p[5];
__constant__ ulonglong2 c_b1p[5];
__constant__ ulonglong2 c_w2p[3][3][5];
__constant__ ps_t c_b2p;

// staging (same layout, contiguous): [0:5) w1p, [5:10) b1p, [10:55) w2p, [55] b2
__device__ ulonglong2 g_packv[56];
__device__ float g_part[NBLK * 4];
__device__ float g_rs2[NB * ND];        // [pair][i][hb]
__device__ float g_csh[NB * ND * 2];    // [pair][half][j][hb]
__device__ unsigned int g_ctr;

// ---------------------------------------------------------------------------
// Kernel 1: row/col sums. grid=1024: block = (batch, row-half), 256 threads.
// ---------------------------------------------------------------------------
__global__ void __launch_bounds__(256) ksums(const float* __restrict__ x,
                                             const float* __restrict__ w1,
                                             const float* __restrict__ b1,
                                             const float* __restrict__ w2,
                                             const float* __restrict__ b2) {
    const int bid = blockIdx.x;
    const int b = bid >> 1;          // batch
    const int h = bid & 1;           // row half
    const int t = threadIdx.x;
    const int w = t >> 5;
    const int l = t & 31;
    const int bi = b >> 1;           // pair
    const int hb = b & 1;            // lane within pair

    if (bid == 0) {   // weight packing into LDC.128-friendly layout
        if (t < 5) {
            g_packv[t]     = make_ulonglong2(pk2(w1[2 * t], w1[2 * t]),
                                             pk2(w1[2 * t + 1], w1[2 * t + 1]));
            g_packv[5 + t] = make_ulonglong2(pk2(b1[2 * t], b1[2 * t]),
                                             pk2(b1[2 * t + 1], b1[2 * t + 1]));
        }
        if (t < 45) {
            const int e = t / 15, d = (t / 5) % 3, cc = t % 5;
            const float wa = w2[(2 * cc) * 9 + d * 3 + e];
            const float wb = w2[(2 * cc + 1) * 9 + d * 3 + e];
            g_packv[10 + t] = make_ulonglong2(pk2(wa, wa), pk2(wb, wb));
        }
        if (t == 0) g_packv[55] = make_ulonglong2(pk2(b2[0], b2[0]), 0ULL);
    }

    __shared__ float scs[8 * 256];
    const float4* __restrict__ xb =
        reinterpret_cast<const float4*>(x + (size_t)b * (ND * ND));

    float ca[8];
#pragma unroll
    for (int k = 0; k < 8; ++k) ca[k] = 0.f;

    const int i0 = 128 * h + 16 * w;
#pragma unroll 4
    for (int ri = 0; ri < 16; ++ri) {
        const int i = i0 + ri;
        float4 v0 = xb[i * 64 + 2 * l];
        float4 v1 = xb[i * 64 + 2 * l + 1];
        ca[0] += v0.x; ca[1] += v0.y; ca[2] += v0.z; ca[3] += v0.w;
        ca[4] += v1.x; ca[5] += v1.y; ca[6] += v1.z; ca[7] += v1.w;
        float rsum = (v0.x + v0.y) + (v0.z + v0.w) + (v1.x + v1.y) + (v1.z + v1.w);
#pragma unroll
        for (int o = 16; o; o >>= 1) rsum += __shfl_xor_sync(0xffffffffu, rsum, o);
        if (l == 0) g_rs2[bi * 512 + i * 2 + hb] = rsum;
    }
#pragma unroll
    for (int k = 0; k < 8; ++k) scs[w * 256 + 8 * l + k] = ca[k];
    __syncthreads();
    float c = 0.f;
#pragma unroll
    for (int ww = 0; ww < 8; ++ww) c += scs[ww * 256 + t];
    g_csh[((bi * 2 + h) * 256 + t) * 2 + hb] = c;
}

// ---------------------------------------------------------------------------
// tap: 10-ch generate + 3-row accumulate, all weights via LDC.128 pairs
// (25 LDC.128 per call instead of 50 LDC.64)
// ---------------------------------------------------------------------------
__device__ __forceinline__ void tap2(ps_t tv, int e, ps_t& A0, ps_t& A1, ps_t& A2) {
#pragma unroll
    for (int cc = 0; cc < 5; ++cc) {
        ulonglong2 wp = c_w1p[cc];
        ulonglong2 bp = c_b1p[cc];
        ps_t ga = relu2(fma2(wp.x, tv, bp.x));
        ps_t gb = relu2(fma2(wp.y, tv, bp.y));
        ulonglong2 p0 = c_w2p[e][0][cc];
        ulonglong2 p1 = c_w2p[e][1][cc];
        ulonglong2 p2 = c_w2p[e][2][cc];
        A0 = fma2(p0.x, ga, A0); A0 = fma2(p0.y, gb, A0);
        A1 = fma2(p1.x, ga, A1); A1 = fma2(p1.y, gb, A1);
        A2 = fma2(p2.x, ga, A2); A2 = fma2(p2.y, gb, A2);
    }
}

// ---------------------------------------------------------------------------
// sweep a p-range of column c. Emits rows i=p-1 for p in [emit_from, pend].
// Bias folding: A1 (and the initial pend1) carry b2v; emit = relu(pend1+A2).
// ---------------------------------------------------------------------------
__device__ __forceinline__ void run_col(
    int c, int pstart, int pend, int emit_from, bool addcorr,
    const ps_t* __restrict__ srs, const ps_t* __restrict__ scs,
    const ps_t (*__restrict__ sW)[4],
    ps_t b2v, float c0, ps_t acc[4]) {

    ps_t wj[4];
#pragma unroll
    for (int k = 0; k < 4; ++k) wj[k] = sW[c][k];

    const bool vm = (c >= 1);
    const bool vp = (c <= 254);
    const ps_t csm = vm ? scs[c - 1] : 0ULL;
    const ps_t cs0 = scs[c];
    const ps_t csp = vp ? scs[c + 1] : 0ULL;

    ps_t pend1 = b2v, a0last = 0ULL, ycol = 0ULL;

#pragma unroll 2
    for (int p = pstart; p <= pend; ++p) {
        ps_t A0 = 0ULL, A1 = b2v, A2 = 0ULL;
        if (p <= 255) {
            const ps_t rsp = srs[p];
            if (vm && (c - 1) <= p) tap2(add2(rsp, csm), 0, A0, A1, A2);
            if (c <= p)             tap2(add2(rsp, cs0), 1, A0, A1, A2);
            if (vp && (c + 1) <= p) tap2(add2(rsp, csp), 2, A0, A1, A2);
        }
        if (p >= emit_from) {
            ps_t y = relu2(add2(pend1, A2));
            ps_t yc = (c <= p + 1) ? y : 0ULL;
            ycol = add2(ycol, yc);
            const ps_t* w4 = sW[p - 1];
#pragma unroll
            for (int k = 0; k < 4; ++k) acc[k] = fma2(yc, w4[k], acc[k]);
        }
        pend1 = add2(A1, a0last);
        a0last = A0;
    }

    if (addcorr) {
        const int rn = (253 - c) > 0 ? (253 - c) : 0;
        const int cn = (c - 2) > 0 ? (c - 2) : 0;
        const float cf = c0 * (float)(rn + cn);
        ycol = add2(ycol, pk2(cf, cf));
    }
#pragma unroll
    for (int k = 0; k < 4; ++k) acc[k] = fma2(ycol, wj[k], acc[k]);
}

// ---------------------------------------------------------------------------
// Kernel 2: band conv + fused fc1 + fused final fc2 (last-block reduction).
// grid = 1024 (= 256 pairs x 4 slices), 128 threads. Natural registers.
// ---------------------------------------------------------------------------
__global__ void __launch_bounds__(128) kband(const float* __restrict__ fc1w,
                                             const float* __restrict__ fc1b,
                                             const float* __restrict__ fc2w,
                                             const float* __restrict__ fc2b,
                                             float* __restrict__ out) {
    const int bid = blockIdx.x;
    const int pair = bid >> 2;
    const int s = bid & 3;

    const int t = threadIdx.x;
    const int w = t >> 5;
    const int lane = t & 31;
    const int q = t;                 // low column of the pair (q, 255-q)

    __shared__ ps_t srs[ND];
    __shared__ ps_t scs[ND];
    __shared__ ps_t sW[ND][4];
    __shared__ ps_t sred[4][4];
    __shared__ int lastf;

#pragma unroll
    for (int r = 0; r < 2; ++r) {
        const int i = t + 128 * r;
        srs[i] = ((const ps_t*)g_rs2)[pair * 256 + i];
        scs[i] = add2(((const ps_t*)g_csh)[(pair * 2 + 0) * 256 + i],
                      ((const ps_t*)g_csh)[(pair * 2 + 1) * 256 + i]);
    }
    const int b0 = 2 * pair;
    for (int idx = t; idx < 1024; idx += 128) {
        const int i = idx >> 2, k = idx & 3;
        sW[i][k] = pk2(fc1w[(size_t)k * 131072 + b0 * 256 + i],
                       fc1w[(size_t)k * 131072 + (b0 + 1) * 256 + i]);
    }
    __syncthreads();

    const ps_t b2v = c_b2p;
    float b2f, b2d; up2(b2v, b2f, b2d);
    const float c0 = fmaxf(b2f, 0.f);

    ps_t acc[4] = {0ULL, 0ULL, 0ULL, 0ULL};

    // virtual timeline: part A = col q over p in [pA0, 256]; part B = col 255-q
    const int pA0 = (q - 3 > 0) ? (q - 3) : 0;
    const int iterA = 257 - pA0;
    const int iterB = q + 5;           // pB0 = 252 - q
    const int tot = iterA + iterB;
    const int v0 = (tot * s) >> 2;
    const int v1 = (tot * (s + 1)) >> 2;

    // part A overlap [v0, min(v1, iterA))
    {
        const int a0 = v0;
        const int a1 = (v1 < iterA) ? v1 : iterA;
        if (a0 < a1) {
            const int pbeg = pA0 + a0;
            const int pend = pA0 + a1 - 1;
            const int pstart = (a0 == 0) ? pbeg : ((pbeg - 2 > 0) ? pbeg - 2 : 0);
            const int ef = (pbeg > 1) ? pbeg : 1;
            run_col(q, pstart, pend, ef, a0 == 0, srs, scs, sW, b2v, c0, acc);
        }
    }
    // part B overlap [max(v0, iterA), v1)
    {
        const int u0 = (v0 > iterA) ? (v0 - iterA) : 0;
        const int u1 = v1 - iterA;
        if (u1 > u0) {
            const int pB0 = 252 - q;
            const int pbeg = pB0 + u0;
            const int pend = pB0 + u1 - 1;
            const int pstart = (u0 == 0) ? pbeg : ((pbeg - 2 > 0) ? pbeg - 2 : 0);
            const int ef = (pbeg > 1) ? pbeg : 1;
            run_col(255 - q, pstart, pend, ef, u0 == 0, srs, scs, sW, b2v, c0, acc);
        }
    }

    // reduce acc across lanes, then across the 4 warps
#pragma unroll
    for (int k = 0; k < 4; ++k) {
#pragma unroll
        for (int o = 16; o; o >>= 1)
            acc[k] = add2(acc[k], __shfl_xor_sync(0xffffffffu, acc[k], o));
    }
    if (lane == 0) {
#pragma unroll
        for (int k = 0; k < 4; ++k) sred[w][k] = acc[k];
    }
    __syncthreads();
    if (t < 4) {
        ps_t sv = add2(add2(sred[0][t], sred[1][t]), add2(sred[2][t], sred[3][t]));
        float lo, hi; up2(sv, lo, hi);
        g_part[bid * 4 + t] = lo + hi;
    }

    // ------- last-block final reduction + fc2 -------
    __threadfence();
    __syncthreads();
    if (t == 0) {
        unsigned int o = atomicAdd(&g_ctr, 1u);
        lastf = (o == (unsigned)(NBLK - 1)) ? 1 : 0;
    }
    __syncthreads();
    if (lastf) {
        float sv = 0.f;
        for (int i = lane; i < NBLK; i += 32) sv += g_part[i * 4 + w];
#pragma unroll
        for (int o = 16; o; o >>= 1) sv += __shfl_xor_sync(0xffffffffu, sv, o);
        __shared__ float fsh[4];
        if (lane == 0) fsh[w] = sv;
        __syncthreads();
        if (t == 0) {
            float h0 = fmaxf(fsh[0] + fc1b[0], 0.f);
            float h1 = fmaxf(fsh[1] + fc1b[1], 0.f);
            float h2 = fmaxf(fsh[2] + fc1b[2], 0.f);
            float h3 = fmaxf(fsh[3] + fc1b[3], 0.f);
            out[0] = fc2w[0] * h0 + fc2w[1] * h1 + fc2w[2] * h2 + fc2w[3] * h3 + fc2b[0];
            out[1] = fc2w[4] * h0 + fc2w[5] * h1 + fc2w[6] * h2 + fc2w[7] * h3 + fc2b[1];
            g_ctr = 0;   // reset for next launch/replay
        }
    }
}

// ---------------------------------------------------------------------------
extern "C" void kernel_launch(void* const* d_in, const int* in_sizes, int n_in,
                              void* d_out, int out_size) {
    const float* x    = (const float*)d_in[0];
    const float* w1   = (const float*)d_in[1];
    const float* b1   = (const float*)d_in[2];
    const float* w2   = (const float*)d_in[3];
    const float* b2   = (const float*)d_in[4];
    const float* fc1w = (const float*)d_in[5];
    const float* fc1b = (const float*)d_in[6];
    const float* fc2w = (const float*)d_in[7];
    const float* fc2b = (const float*)d_in[8];

    ksums<<<2 * NB, 256>>>(x, w1, b1, w2, b2);

    void* gp = nullptr;
    cudaGetSymbolAddress(&gp, g_packv);
    cudaMemcpyToSymbolAsync(c_w1p, gp, 5 * sizeof(ulonglong2), 0,
                            cudaMemcpyDeviceToDevice, 0);
    cudaMemcpyToSymbolAsync(c_b1p, (char*)gp + 5 * sizeof(ulonglong2),
                            5 * sizeof(ulonglong2), 0, cudaMemcpyDeviceToDevice, 0);
    cudaMemcpyToSymbolAsync(c_w2p, (char*)gp + 10 * sizeof(ulonglong2),
                            45 * sizeof(ulonglong2), 0, cudaMemcpyDeviceToDevice, 0);
    cudaMemcpyToSymbolAsync(c_b2p, (char*)gp + 55 * sizeof(ulonglong2),
                            sizeof(ps_t), 0, cudaMemcpyDeviceToDevice, 0);

    kband<<<NBLK, 128>>>(fc1w, fc1b, fc2w, fc2b, (float*)d_out);
}